// round 2
// baseline (speedup 1.0000x reference)
#include <cuda_runtime.h>

#define NFFT 640
#define HOP  320
#define NF   321            // freq bins
#define NT   301            // time frames
#define TLEN 96000
#define NCHF 17             // 16 x-channels + ref(b=0)
#define NFRF (NCHF*NT)      // 5117 forward frames
#define MINV (7*NT)         // 2107 inverse frames
#define LPAD 96640
#define FT   (NF*NT)        // 96621
#define OFF_FEATS 768000

#define TWO_PI 6.283185307179586f

// ---------------- scratch (device globals; no allocation allowed) -------------
__device__ float  g_win[NFFT];
__device__ float  g_invw[LPAD];
__device__ float2 g_WfT[NFFT*NF];      // forward DFT, [n][f] = (cos, -sin)(2pi f n/640)
__device__ float2 g_Wi[NF*NFFT];       // inverse, [k][n] = ck*win[n]/640 * (cos, -sin)
__device__ float  g_frames[NFRF*NFFT]; // windowed frames
__device__ float2 g_S[NF*NFRF];        // STFT, freq-major [f][m], m = ch*NT + t
__device__ float2 g_rp[323*309];       // padded refS (b=0)
__device__ float2 g_est[7*FT];         // est[m][f][t]
__device__ float  g_y[MINV*NFFT];      // inverse frames (windowed)

// ---------------- init: twiddles + window + inverse window-sum ----------------
__global__ void k_twiddle() {
    int idx = blockIdx.x*blockDim.x + threadIdx.x;
    if (idx >= NFFT*NF) return;
    int n = idx / NF;
    int k = idx - n*NF;
    int r = (n*k) % NFFT;
    float s, c;
    __sincosf(0.0f, &s, &c); // dummy to keep compiler happy? (removed below)
    sincosf(TWO_PI * (float)r / (float)NFFT, &s, &c);
    g_WfT[n*NF + k] = make_float2(c, -s);
    float win = 0.5f - 0.5f*cosf(TWO_PI * (float)n / (float)NFFT);
    if (k == 0) g_win[n] = win;
    float ck = (k == 0 || k == NF-1) ? 1.0f : 2.0f;
    float sc = ck * win / (float)NFFT;
    g_Wi[k*NFFT + n] = make_float2(sc*c, -sc*s);
}

__global__ void k_invw() {
    int sp = blockIdx.x*blockDim.x + threadIdx.x;
    if (sp >= LPAD) return;
    float wsum = 0.0f;
    int t1 = sp / HOP;
    #pragma unroll
    for (int d = 0; d < 2; d++) {
        int t = t1 - d;
        if (t >= 0 && t < NT) {
            int n = sp - t*HOP;
            if (n >= 0 && n < NFFT) {
                float w = 0.5f - 0.5f*cosf(TWO_PI * (float)n / (float)NFFT);
                wsum += w*w;
            }
        }
    }
    g_invw[sp] = (wsum > 1e-11f) ? (1.0f/wsum) : 1.0f;
}

// ---------------- framing ----------------
__global__ void k_frames(const float* __restrict__ x, const float* __restrict__ ref) {
    int idx = blockIdx.x*blockDim.x + threadIdx.x;
    if (idx >= NFRF*NFFT) return;
    int m = idx / NFFT;
    int n = idx - m*NFFT;
    int ch = m / NT;
    int t  = m - ch*NT;
    const float* sig = (ch < 16) ? (x + ch*TLEN) : ref;   // ref = ref_g[0]
    int p = t*HOP + n - HOP;   // center padding
    float v = (p >= 0 && p < TLEN) ? sig[p] : 0.0f;
    g_frames[idx] = v * g_win[n];
}

// ---------------- forward DFT GEMM:  S[f][m] = sum_n frames[m][n] * WfT[n][f] --
#define FBM 128
#define FBN 32
#define FBK 32
__global__ void __launch_bounds__(256) k_gemm_fwd() {
    __shared__ float  As[FBK][FBM+1];
    __shared__ float2 Ws[FBK][FBN];
    int m0 = blockIdx.x * FBM;
    int f0 = blockIdx.y * FBN;
    int lid = threadIdx.x;
    int tx = lid & 15, ty = lid >> 4;

    float2 acc[8][2];
    #pragma unroll
    for (int i = 0; i < 8; i++)
        #pragma unroll
        for (int j = 0; j < 2; j++) acc[i][j] = make_float2(0.f, 0.f);

    for (int k0 = 0; k0 < NFFT; k0 += FBK) {
        #pragma unroll
        for (int rep = 0; rep < 16; rep++) {
            int e = rep*256 + lid;
            int k = e & 31, ml = e >> 5;
            int m = m0 + ml;
            As[k][ml] = (m < NFRF) ? g_frames[m*NFFT + k0 + k] : 0.0f;
        }
        #pragma unroll
        for (int rep = 0; rep < 4; rep++) {
            int e = rep*256 + lid;
            int j = e & 31, k = e >> 5;
            int f = f0 + j;
            Ws[k][j] = (f < NF) ? g_WfT[(k0+k)*NF + f] : make_float2(0.f, 0.f);
        }
        __syncthreads();
        #pragma unroll
        for (int k = 0; k < FBK; k++) {
            float a[8];
            #pragma unroll
            for (int i = 0; i < 8; i++) a[i] = As[k][i*16 + tx];
            float2 w0 = Ws[k][ty];
            float2 w1 = Ws[k][16 + ty];
            #pragma unroll
            for (int i = 0; i < 8; i++) {
                acc[i][0].x += a[i]*w0.x;  acc[i][0].y += a[i]*w0.y;
                acc[i][1].x += a[i]*w1.x;  acc[i][1].y += a[i]*w1.y;
            }
        }
        __syncthreads();
    }
    #pragma unroll
    for (int j = 0; j < 2; j++) {
        int f = f0 + j*16 + ty;
        if (f < NF) {
            #pragma unroll
            for (int i = 0; i < 8; i++) {
                int m = m0 + i*16 + tx;
                if (m < NFRF) g_S[f*NFRF + m] = acc[i][j];
            }
        }
    }
}

// ---------------- covariance features ----------------
__global__ void k_cov(float* __restrict__ out) {
    int idx = blockIdx.x*blockDim.x + threadIdx.x;
    if (idx >= 2*FT) return;
    int t = idx % NT;
    int f = (idx / NT) % NF;
    int b = idx / FT;
    float2 S[8];
    #pragma unroll
    for (int c = 0; c < 8; c++)
        S[c] = g_S[f*NFRF + (b*8 + c)*NT + t];
    float* o = out + OFF_FEATS + (b*74)*FT + f*NT + t;
    int p = 0;
    #pragma unroll
    for (int i = 0; i < 8; i++) {
        #pragma unroll
        for (int j = i; j < 8; j++) {
            float re = S[i].x*S[j].x + S[i].y*S[j].y;   // S_i * conj(S_j)
            float im = S[i].y*S[j].x - S[i].x*S[j].y;
            o[(2*p    )*FT] = re;
            o[(2*p + 1)*FT] = im;
            p++;
        }
    }
    o[72*FT] = S[3].x;
    o[73*FT] = S[3].y;
}

// ---------------- padded refS (b=0) ----------------
__global__ void k_refpad() {
    int idx = blockIdx.x*blockDim.x + threadIdx.x;
    if (idx >= 323*309) return;
    int fp = idx / 309, tp = idx - fp*309;
    int f = fp - 1, t = tp - 4;
    float2 v = make_float2(0.f, 0.f);
    if (f >= 0 && f < NF && t >= 0 && t < NT)
        v = g_S[f*NFRF + 16*NT + t];
    g_rp[idx] = v;
}

// ---------------- deep filtering (b=0 only) ----------------
__global__ void k_deepfilter(const float2* __restrict__ rtf) {
    int idx = blockIdx.x*blockDim.x + threadIdx.x;
    if (idx >= 7*FT) return;
    int t = idx % NT;
    int f = (idx / NT) % NF;
    int m = idx / FT;
    const float2* rbase = rtf + m*27*FT + f*NT + t;  // b=0: [m][27][F][T] float2
    float2 acc = make_float2(0.f, 0.f);
    #pragma unroll
    for (int ki = 0; ki < 3; ki++) {
        #pragma unroll
        for (int kj = 0; kj < 9; kj++) {
            float2 r = rbase[(ki*9 + kj)*FT];
            float2 p = g_rp[(f + ki)*309 + (t + kj)];
            acc.x += r.x*p.x - r.y*p.y;
            acc.y += r.x*p.y + r.y*p.x;
        }
    }
    g_est[idx] = acc;
}

// ---------------- inverse DFT GEMM: y[R][n] = sum_k est.x*Wi.x + est.y*Wi.y ----
#define IBM 64
#define IBN 64
#define IBK 16
__global__ void __launch_bounds__(256) k_gemm_inv() {
    __shared__ float2 As[IBK][IBM];
    __shared__ float2 Ws[IBK][IBN];
    int r0 = blockIdx.x * IBM;
    int n0 = blockIdx.y * IBN;
    int lid = threadIdx.x;
    int tx = lid & 15, ty = lid >> 4;

    float acc[4][4];
    #pragma unroll
    for (int i = 0; i < 4; i++)
        #pragma unroll
        for (int j = 0; j < 4; j++) acc[i][j] = 0.0f;

    for (int k0 = 0; k0 < NF; k0 += IBK) {
        #pragma unroll
        for (int rep = 0; rep < 4; rep++) {
            int e = rep*256 + lid;
            int r = e & 63, k = e >> 6;
            int R = r0 + r, kk = k0 + k;
            float2 v = make_float2(0.f, 0.f);
            if (R < MINV && kk < NF) {
                int mm = R / NT, tt = R - mm*NT;
                v = g_est[(mm*NF + kk)*NT + tt];
            }
            As[k][r] = v;
        }
        #pragma unroll
        for (int rep = 0; rep < 4; rep++) {
            int e = rep*256 + lid;
            int n = e & 63, k = e >> 6;
            int kk = k0 + k;
            Ws[k][n] = (kk < NF) ? g_Wi[kk*NFFT + n0 + n] : make_float2(0.f, 0.f);
        }
        __syncthreads();
        #pragma unroll
        for (int k = 0; k < IBK; k++) {
            float2 a[4], w[4];
            #pragma unroll
            for (int i = 0; i < 4; i++) a[i] = As[k][i*16 + ty];
            #pragma unroll
            for (int j = 0; j < 4; j++) w[j] = Ws[k][j*16 + tx];
            #pragma unroll
            for (int i = 0; i < 4; i++)
                #pragma unroll
                for (int j = 0; j < 4; j++)
                    acc[i][j] += a[i].x*w[j].x + a[i].y*w[j].y;
        }
        __syncthreads();
    }
    #pragma unroll
    for (int i = 0; i < 4; i++) {
        int R = r0 + i*16 + ty;
        if (R < MINV) {
            #pragma unroll
            for (int j = 0; j < 4; j++) {
                int n = n0 + j*16 + tx;
                g_y[R*NFFT + n] = acc[i][j];
            }
        }
    }
}

// ---------------- overlap-add + interleave output ----------------
__global__ void k_ola(const float* __restrict__ ref, float* __restrict__ out) {
    int s = blockIdx.x*blockDim.x + threadIdx.x;
    if (s >= TLEN) return;
    int sp = s + HOP;                 // position in uncropped signal
    int t1 = sp / HOP;                // in [1, 300]
    int n1 = sp - t1*HOP;             // [0, 320)
    int t0 = t1 - 1;
    int nn0 = n1 + HOP;               // [320, 640)
    float iw = g_invw[sp];
    float* o = out + s*8;
    #pragma unroll
    for (int m = 0; m < 7; m++) {
        float v = (g_y[(m*NT + t0)*NFFT + nn0] + g_y[(m*NT + t1)*NFFT + n1]) * iw;
        o[m < 3 ? m : m + 1] = v;
    }
    o[3] = ref[s];
}

// ---------------- launch ----------------
extern "C" void kernel_launch(void* const* d_in, const int* in_sizes, int n_in,
                              void* d_out, int out_size) {
    const float*  x   = (const float*)d_in[0];
    const float2* rtf = (const float2*)d_in[1];  // [B][7][3][9][F][T][2]; b=0 slice
    const float*  ref = (const float*)d_in[2];   // [2][1][T]; b=0 slice
    float* out = (float*)d_out;

    k_twiddle<<<(NFFT*NF + 255)/256, 256>>>();
    k_invw<<<(LPAD + 255)/256, 256>>>();
    k_frames<<<(NFRF*NFFT + 255)/256, 256>>>(x, ref);
    {
        dim3 g((NFRF + FBM - 1)/FBM, (NF + FBN - 1)/FBN);
        k_gemm_fwd<<<g, 256>>>();
    }
    k_cov<<<(2*FT + 255)/256, 256>>>(out);
    k_refpad<<<(323*309 + 255)/256, 256>>>();
    k_deepfilter<<<(7*FT + 255)/256, 256>>>(rtf);
    {
        dim3 g((MINV + IBM - 1)/IBM, NFFT/IBN);
        k_gemm_inv<<<g, 256>>>();
    }
    k_ola<<<(TLEN + 255)/256, 256>>>(ref, out);
}

// round 6
// speedup vs baseline: 1.5498x; 1.5498x over previous
#include <cuda_runtime.h>

#define NFFT 640
#define HOP  320
#define NF   321            // freq bins
#define NT   301            // time frames
#define TLEN 96000
#define NCHF 17             // 16 x-channels + ref(b=0)
#define NFRF (NCHF*NT)      // 5117 forward frames
#define MINV (7*NT)         // 2107 inverse frames
#define LPAD 96640
#define FT   (NF*NT)        // 96621
#define OFF_FEATS 768000

#define TWO_PI 6.283185307179586f

// ---------------- scratch (device globals; no allocation allowed) -------------
__device__ float  g_win[NFFT];
__device__ float  g_invw[LPAD];
__device__ float2 g_Wi[NF*NFFT];       // inverse, [k][n] = ck*win[n]/640 * (cos, -sin)
__device__ float2 g_ct[32*20*20];      // stage1 twiddle: [n1][n2][r] = (cos,-sin)(2pi r n/640), n=n1+32n2  (NO window!)
__device__ float2 g_W32[32*17];        // stage2 twiddle: [n1][q] = (cos,-sin)(2pi q n1/32)
__device__ float  g_framesT[NFFT*NFRF];// transposed windowed frames [n][m]
__device__ float2 g_Z[640*NFRF];       // stage1 output, [(r*32+n1)][m]
__device__ float2 g_S[NF*NFRF];        // STFT, freq-major [f][m], m = ch*NT + t
__device__ float2 g_rp[323*309];       // padded refS (b=0)
__device__ float2 g_est[7*FT];         // est[m][f][t]
__device__ float  g_y[MINV*NFFT];      // inverse frames (windowed)

// ---------------- init: window + inverse DFT matrix ----------------
__global__ void k_init1() {
    int idx = blockIdx.x*blockDim.x + threadIdx.x;
    if (idx >= NFFT*NF) return;
    int n = idx / NF;
    int k = idx - n*NF;
    int r = (n*k) % NFFT;
    float s, c;
    sincosf(TWO_PI * (float)r / (float)NFFT, &s, &c);
    float win = 0.5f - 0.5f*cosf(TWO_PI * (float)n / (float)NFFT);
    if (k == 0) g_win[n] = win;
    float ck = (k == 0 || k == NF-1) ? 1.0f : 2.0f;
    float sc = ck * win / (float)NFFT;
    g_Wi[k*NFFT + n] = make_float2(sc*c, -sc*s);
}

// ---------------- init: factored-DFT tables (pure twiddles) ----------------
__global__ void k_tab() {
    int idx = blockIdx.x*blockDim.x + threadIdx.x;
    if (idx < 32*20*20) {
        int n1 = idx / 400;
        int rem = idx - n1*400;
        int n2 = rem / 20;
        int r  = rem - n2*20;
        int n = n1 + 32*n2;
        float s, c;
        sincosf(TWO_PI * (float)((r*n) % NFFT) / (float)NFFT, &s, &c);
        g_ct[idx] = make_float2(c, -s);        // window is applied in k_framesT only
    } else if (idx < 32*20*20 + 32*17) {
        int e = idx - 32*20*20;
        int n1 = e / 17, q = e - n1*17;
        float s, c;
        sincosf(TWO_PI * (float)((q*n1) % 32) / 32.0f, &s, &c);
        g_W32[e] = make_float2(c, -s);
    }
}

__global__ void k_invw() {
    int sp = blockIdx.x*blockDim.x + threadIdx.x;
    if (sp >= LPAD) return;
    float wsum = 0.0f;
    int t1 = sp / HOP;
    #pragma unroll
    for (int d = 0; d < 2; d++) {
        int t = t1 - d;
        if (t >= 0 && t < NT) {
            int n = sp - t*HOP;
            if (n >= 0 && n < NFFT) {
                float w = 0.5f - 0.5f*cosf(TWO_PI * (float)n / (float)NFFT);
                wsum += w*w;
            }
        }
    }
    g_invw[sp] = (wsum > 1e-11f) ? (1.0f/wsum) : 1.0f;
}

// ---------------- framing (windowed, transposed output [n][m]) ----------------
__global__ void k_framesT(const float* __restrict__ x, const float* __restrict__ ref) {
    __shared__ float s[32][33];
    int tx = threadIdx.x, ty = threadIdx.y;   // block (32,8)
    int m0 = blockIdx.x * 32;
    int n0 = blockIdx.y * 32;
    int n = n0 + tx;
    float w = g_win[n];
    #pragma unroll
    for (int r4 = 0; r4 < 4; r4++) {
        int mr = ty + r4*8;
        int m = m0 + mr;
        float v = 0.0f;
        if (m < NFRF) {
            int ch = m / NT;
            int t  = m - ch*NT;
            const float* sig = (ch < 16) ? (x + ch*TLEN) : ref;
            int p = t*HOP + n - HOP;
            if (p >= 0 && p < TLEN) v = sig[p];
        }
        s[mr][tx] = v * w;
    }
    __syncthreads();
    int m = m0 + tx;
    if (m < NFRF) {
        #pragma unroll
        for (int r4 = 0; r4 < 4; r4++) {
            int nr = ty + r4*8;
            g_framesT[(n0 + nr)*NFRF + m] = s[tx][nr];
        }
    }
}

// ---------------- stage 1: Z[n1][r][m] = sum_n2 frames[m][n1+32n2]*ct[n1][n2][r]
// grid (10 m-tiles, 32 n1), block 256; M-tile 512 (2 m per thread)
__global__ void __launch_bounds__(256) k_stage1() {
    __shared__ float  As[20][512];
    __shared__ float2 cts[400];
    int m0 = blockIdx.x * 512;
    int n1 = blockIdx.y;
    int lid = threadIdx.x;

    #pragma unroll
    for (int i = 0; i < 40; i++) {
        int e = i*256 + lid;
        int n2 = e >> 9, ml = e & 511;
        int m = m0 + ml;
        As[n2][ml] = (m < NFRF) ? g_framesT[(n1 + 32*n2)*NFRF + m] : 0.0f;
    }
    #pragma unroll
    for (int i = 0; i < 2; i++) {
        int e = i*256 + lid;
        if (e < 400) cts[e] = g_ct[n1*400 + e];
    }
    __syncthreads();

    float2 acc[2][20];
    #pragma unroll
    for (int i = 0; i < 2; i++)
        #pragma unroll
        for (int r = 0; r < 20; r++) acc[i][r] = make_float2(0.f, 0.f);

    #pragma unroll
    for (int n2 = 0; n2 < 20; n2++) {
        float a0 = As[n2][lid];
        float a1 = As[n2][lid + 256];
        #pragma unroll
        for (int r = 0; r < 20; r++) {
            float2 c = cts[n2*20 + r];
            acc[0][r].x += a0*c.x;  acc[0][r].y += a0*c.y;
            acc[1][r].x += a1*c.x;  acc[1][r].y += a1*c.y;
        }
    }

    int ma = m0 + lid, mb = m0 + lid + 256;
    #pragma unroll
    for (int r = 0; r < 20; r++) {
        int base = (r*32 + n1)*NFRF;
        if (ma < NFRF) g_Z[base + ma] = acc[0][r];
        if (mb < NFRF) g_Z[base + mb] = acc[1][r];
    }
}

// ---------------- stage 2: S[r+20q][m] = sum_n1 Z[n1][r][m] * W32[n1][q]
// grid (20 m-tiles, 20 r), block 256; M-tile 256
__global__ void __launch_bounds__(256) k_stage2() {
    __shared__ float2 Zs[16][256];
    __shared__ float2 Bs[32*17];
    int m0 = blockIdx.x * 256;
    int r  = blockIdx.y;
    int lid = threadIdx.x;

    #pragma unroll
    for (int e = lid; e < 32*17; e += 256) Bs[e] = g_W32[e];

    float2 acc[17];
    #pragma unroll
    for (int q = 0; q < 17; q++) acc[q] = make_float2(0.f, 0.f);

    #pragma unroll
    for (int kh = 0; kh < 2; kh++) {
        __syncthreads();
        #pragma unroll
        for (int i = 0; i < 16; i++) {
            int e = i*256 + lid;
            int k = e >> 8, ml = e & 255;
            int m = m0 + ml;
            Zs[k][ml] = (m < NFRF) ? g_Z[(r*32 + kh*16 + k)*NFRF + m]
                                   : make_float2(0.f, 0.f);
        }
        __syncthreads();
        #pragma unroll
        for (int k = 0; k < 16; k++) {
            float2 a = Zs[k][lid];
            int kg = kh*16 + k;
            #pragma unroll
            for (int q = 0; q < 17; q++) {
                float2 b = Bs[kg*17 + q];
                acc[q].x += a.x*b.x - a.y*b.y;
                acc[q].y += a.x*b.y + a.y*b.x;
            }
        }
    }

    int m = m0 + lid;
    if (m < NFRF) {
        #pragma unroll
        for (int q = 0; q < 17; q++) {
            int f = r + 20*q;
            if (f < NF) g_S[f*NFRF + m] = acc[q];
        }
    }
}

// ---------------- covariance features ----------------
__global__ void k_cov(float* __restrict__ out) {
    int idx = blockIdx.x*blockDim.x + threadIdx.x;
    if (idx >= 2*FT) return;
    int t = idx % NT;
    int f = (idx / NT) % NF;
    int b = idx / FT;
    float2 S[8];
    #pragma unroll
    for (int c = 0; c < 8; c++)
        S[c] = g_S[f*NFRF + (b*8 + c)*NT + t];
    float* o = out + OFF_FEATS + (b*74)*FT + f*NT + t;
    int p = 0;
    #pragma unroll
    for (int i = 0; i < 8; i++) {
        #pragma unroll
        for (int j = i; j < 8; j++) {
            float re = S[i].x*S[j].x + S[i].y*S[j].y;   // S_i * conj(S_j)
            float im = S[i].y*S[j].x - S[i].x*S[j].y;
            o[(2*p    )*FT] = re;
            o[(2*p + 1)*FT] = im;
            p++;
        }
    }
    o[72*FT] = S[3].x;
    o[73*FT] = S[3].y;
}

// ---------------- padded refS (b=0) ----------------
__global__ void k_refpad() {
    int idx = blockIdx.x*blockDim.x + threadIdx.x;
    if (idx >= 323*309) return;
    int fp = idx / 309, tp = idx - fp*309;
    int f = fp - 1, t = tp - 4;
    float2 v = make_float2(0.f, 0.f);
    if (f >= 0 && f < NF && t >= 0 && t < NT)
        v = g_S[f*NFRF + 16*NT + t];
    g_rp[idx] = v;
}

// ---------------- deep filtering (b=0 only) ----------------
__global__ void k_deepfilter(const float2* __restrict__ rtf) {
    int idx = blockIdx.x*blockDim.x + threadIdx.x;
    if (idx >= 7*FT) return;
    int t = idx % NT;
    int f = (idx / NT) % NF;
    int m = idx / FT;
    const float2* rbase = rtf + m*27*FT + f*NT + t;  // b=0: [m][27][F][T] float2
    float2 acc = make_float2(0.f, 0.f);
    #pragma unroll
    for (int ki = 0; ki < 3; ki++) {
        #pragma unroll
        for (int kj = 0; kj < 9; kj++) {
            float2 r = rbase[(ki*9 + kj)*FT];
            float2 p = g_rp[(f + ki)*309 + (t + kj)];
            acc.x += r.x*p.x - r.y*p.y;
            acc.y += r.x*p.y + r.y*p.x;
        }
    }
    g_est[idx] = acc;
}

// ---------------- inverse DFT GEMM: y[R][n] = sum_k est.x*Wi.x + est.y*Wi.y ----
#define IBM 64
#define IBN 64
#define IBK 16
__global__ void __launch_bounds__(256) k_gemm_inv() {
    __shared__ float2 As[IBK][IBM];
    __shared__ float2 Ws[IBK][IBN];
    int r0 = blockIdx.x * IBM;
    int n0 = blockIdx.y * IBN;
    int lid = threadIdx.x;
    int tx = lid & 15, ty = lid >> 4;

    float acc[4][4];
    #pragma unroll
    for (int i = 0; i < 4; i++)
        #pragma unroll
        for (int j = 0; j < 4; j++) acc[i][j] = 0.0f;

    for (int k0 = 0; k0 < NF; k0 += IBK) {
        #pragma unroll
        for (int rep = 0; rep < 4; rep++) {
            int e = rep*256 + lid;
            int r = e & 63, k = e >> 6;
            int R = r0 + r, kk = k0 + k;
            float2 v = make_float2(0.f, 0.f);
            if (R < MINV && kk < NF) {
                int mm = R / NT, tt = R - mm*NT;
                v = g_est[(mm*NF + kk)*NT + tt];
            }
            As[k][r] = v;
        }
        #pragma unroll
        for (int rep = 0; rep < 4; rep++) {
            int e = rep*256 + lid;
            int n = e & 63, k = e >> 6;
            int kk = k0 + k;
            Ws[k][n] = (kk < NF) ? g_Wi[kk*NFFT + n0 + n] : make_float2(0.f, 0.f);
        }
        __syncthreads();
        #pragma unroll
        for (int k = 0; k < IBK; k++) {
            float2 a[4], w[4];
            #pragma unroll
            for (int i = 0; i < 4; i++) a[i] = As[k][i*16 + ty];
            #pragma unroll
            for (int j = 0; j < 4; j++) w[j] = Ws[k][j*16 + tx];
            #pragma unroll
            for (int i = 0; i < 4; i++)
                #pragma unroll
                for (int j = 0; j < 4; j++)
                    acc[i][j] += a[i].x*w[j].x + a[i].y*w[j].y;
        }
        __syncthreads();
    }
    #pragma unroll
    for (int i = 0; i < 4; i++) {
        int R = r0 + i*16 + ty;
        if (R < MINV) {
            #pragma unroll
            for (int j = 0; j < 4; j++) {
                int n = n0 + j*16 + tx;
                g_y[R*NFFT + n] = acc[i][j];
            }
        }
    }
}

// ---------------- overlap-add + interleave output ----------------
__global__ void k_ola(const float* __restrict__ ref, float* __restrict__ out) {
    int s = blockIdx.x*blockDim.x + threadIdx.x;
    if (s >= TLEN) return;
    int sp = s + HOP;                 // position in uncropped signal
    int t1 = sp / HOP;                // in [1, 300]
    int n1 = sp - t1*HOP;             // [0, 320)
    int t0 = t1 - 1;
    int nn0 = n1 + HOP;               // [320, 640)
    float iw = g_invw[sp];
    float* o = out + s*8;
    #pragma unroll
    for (int m = 0; m < 7; m++) {
        float v = (g_y[(m*NT + t0)*NFFT + nn0] + g_y[(m*NT + t1)*NFFT + n1]) * iw;
        o[m < 3 ? m : m + 1] = v;
    }
    o[3] = ref[s];
}

// ---------------- launch ----------------
extern "C" void kernel_launch(void* const* d_in, const int* in_sizes, int n_in,
                              void* d_out, int out_size) {
    const float*  x   = (const float*)d_in[0];
    const float2* rtf = (const float2*)d_in[1];  // [B][7][3][9][F][T][2]; b=0 slice
    const float*  ref = (const float*)d_in[2];   // [2][1][T]; b=0 slice
    float* out = (float*)d_out;

    k_init1<<<(NFFT*NF + 255)/256, 256>>>();
    k_tab<<<(32*20*20 + 32*17 + 255)/256, 256>>>();
    k_invw<<<(LPAD + 255)/256, 256>>>();
    {
        dim3 g((NFRF + 31)/32, NFFT/32);
        k_framesT<<<g, dim3(32, 8)>>>(x, ref);
    }
    {
        dim3 g((NFRF + 511)/512, 32);
        k_stage1<<<g, 256>>>();
    }
    {
        dim3 g((NFRF + 255)/256, 20);
        k_stage2<<<g, 256>>>();
    }
    k_cov<<<(2*FT + 255)/256, 256>>>(out);
    k_refpad<<<(323*309 + 255)/256, 256>>>();
    k_deepfilter<<<(7*FT + 255)/256, 256>>>(rtf);
    {
        dim3 g((MINV + IBM - 1)/IBM, NFFT/IBN);
        k_gemm_inv<<<g, 256>>>();
    }
    k_ola<<<(TLEN + 255)/256, 256>>>(ref, out);
}

// round 7
// speedup vs baseline: 2.3722x; 1.5306x over previous
#include <cuda_runtime.h>

#define NFFT 640
#define HOP  320
#define NF   321            // freq bins
#define NT   301            // time frames
#define TLEN 96000
#define NCHF 17             // 16 x-channels + ref(b=0)
#define NFRF (NCHF*NT)      // 5117 forward frames
#define MINV (7*NT)         // 2107 inverse frames
#define LPAD 96640
#define FT   (NF*NT)        // 96621
#define OFF_FEATS 768000

#define TWO_PI 6.283185307179586f

// ---------------- scratch (device globals; no allocation allowed) -------------
__device__ float  g_win[NFFT];
__device__ float  g_invw[LPAD];
__device__ float2 g_ct[32*20*20];      // fwd stage1 twiddle: [n1][n2][r] = (cos,-sin)(2pi r n/640)
__device__ float2 g_W32[32*17];        // fwd stage2 twiddle: [n1][q] = (cos,-sin)(2pi q n1/32)
__device__ float2 g_TA[20*17*32];      // inv stageA: [r][q][n1] = ck*(cos,+sin)(2pi k n1/640), k=20q+r (0 if k>320)
__device__ float2 g_TB[20*20];         // inv stageB: [r][n2] = (cos,+sin)(2pi r n2/20)
__device__ float  g_framesT[NFFT*NFRF];// transposed windowed frames [n][m]
__device__ float2 g_Z[640*NFRF];       // fwd stage1 output, [(r*32+n1)][m]
__device__ float2 g_S[NF*NFRF];        // STFT, freq-major [f][m], m = ch*NT + t
__device__ float2 g_rp[323*309];       // padded refS (b=0)
__device__ float2 g_estF[NF*MINV];     // est freq-major [k][R], R = m*NT + t
__device__ float2 g_A1[640*MINV];      // inv stageA output, [(r*32+n1)][R]
__device__ float  g_y[MINV*NFFT];      // inverse frames (pre-OLA, windowed)

// ---------------- init: all twiddle tables + window ----------------
__global__ void k_tab() {
    int idx = blockIdx.x*blockDim.x + threadIdx.x;
    if (idx < 32*20*20) {
        // fwd stage1: pure twiddle
        int n1 = idx / 400;
        int rem = idx - n1*400;
        int n2 = rem / 20;
        int r  = rem - n2*20;
        int n = n1 + 32*n2;
        float s, c;
        sincosf(TWO_PI * (float)((r*n) % NFFT) / (float)NFFT, &s, &c);
        g_ct[idx] = make_float2(c, -s);
    } else if (idx < 12800 + 544) {
        int e = idx - 12800;
        int n1 = e / 17, q = e - n1*17;
        float s, c;
        sincosf(TWO_PI * (float)((q*n1) % 32) / 32.0f, &s, &c);
        g_W32[e] = make_float2(c, -s);
    } else if (idx < 12800 + 544 + 10880) {
        // inv stageA: ck * e^{+2pi i k n1/640}, k = 20q+r
        int e = idx - 13344;
        int r = e / 544;
        int rem = e - r*544;
        int q = rem / 32, n1 = rem - q*32;
        int k = 20*q + r;
        float2 v = make_float2(0.f, 0.f);
        if (k <= 320) {
            float ck = (k == 0 || k == 320) ? 1.0f : 2.0f;
            float s, c;
            sincosf(TWO_PI * (float)((k*n1) % NFFT) / (float)NFFT, &s, &c);
            v = make_float2(ck*c, ck*s);
        }
        g_TA[e] = v;
    } else if (idx < 12800 + 544 + 10880 + 400) {
        // inv stageB: e^{+2pi i r n2/20}
        int e = idx - 24224;
        int r = e / 20, n2 = e - r*20;
        float s, c;
        sincosf(TWO_PI * (float)((r*n2) % 20) / 20.0f, &s, &c);
        g_TB[e] = make_float2(c, s);
    } else if (idx < 12800 + 544 + 10880 + 400 + NFFT) {
        int n = idx - 24624;
        g_win[n] = 0.5f - 0.5f*cosf(TWO_PI * (float)n / (float)NFFT);
    }
}

__global__ void k_invw() {
    int sp = blockIdx.x*blockDim.x + threadIdx.x;
    if (sp >= LPAD) return;
    float wsum = 0.0f;
    int t1 = sp / HOP;
    #pragma unroll
    for (int d = 0; d < 2; d++) {
        int t = t1 - d;
        if (t >= 0 && t < NT) {
            int n = sp - t*HOP;
            if (n >= 0 && n < NFFT) {
                float w = 0.5f - 0.5f*cosf(TWO_PI * (float)n / (float)NFFT);
                wsum += w*w;
            }
        }
    }
    g_invw[sp] = (wsum > 1e-11f) ? (1.0f/wsum) : 1.0f;
}

// ---------------- framing (windowed, transposed output [n][m]) ----------------
__global__ void k_framesT(const float* __restrict__ x, const float* __restrict__ ref) {
    __shared__ float s[32][33];
    int tx = threadIdx.x, ty = threadIdx.y;   // block (32,8)
    int m0 = blockIdx.x * 32;
    int n0 = blockIdx.y * 32;
    int n = n0 + tx;
    float w = g_win[n];
    #pragma unroll
    for (int r4 = 0; r4 < 4; r4++) {
        int mr = ty + r4*8;
        int m = m0 + mr;
        float v = 0.0f;
        if (m < NFRF) {
            int ch = m / NT;
            int t  = m - ch*NT;
            const float* sig = (ch < 16) ? (x + ch*TLEN) : ref;
            int p = t*HOP + n - HOP;
            if (p >= 0 && p < TLEN) v = sig[p];
        }
        s[mr][tx] = v * w;
    }
    __syncthreads();
    int m = m0 + tx;
    if (m < NFRF) {
        #pragma unroll
        for (int r4 = 0; r4 < 4; r4++) {
            int nr = ty + r4*8;
            g_framesT[(n0 + nr)*NFRF + m] = s[tx][nr];
        }
    }
}

// ---------------- fwd stage 1: Z[n1][r][m] = sum_n2 frames[m][n1+32n2]*ct[n1][n2][r]
__global__ void __launch_bounds__(256) k_stage1() {
    __shared__ float  As[20][512];
    __shared__ float2 cts[400];
    int m0 = blockIdx.x * 512;
    int n1 = blockIdx.y;
    int lid = threadIdx.x;

    #pragma unroll
    for (int i = 0; i < 40; i++) {
        int e = i*256 + lid;
        int n2 = e >> 9, ml = e & 511;
        int m = m0 + ml;
        As[n2][ml] = (m < NFRF) ? g_framesT[(n1 + 32*n2)*NFRF + m] : 0.0f;
    }
    #pragma unroll
    for (int i = 0; i < 2; i++) {
        int e = i*256 + lid;
        if (e < 400) cts[e] = g_ct[n1*400 + e];
    }
    __syncthreads();

    float2 acc[2][20];
    #pragma unroll
    for (int i = 0; i < 2; i++)
        #pragma unroll
        for (int r = 0; r < 20; r++) acc[i][r] = make_float2(0.f, 0.f);

    #pragma unroll
    for (int n2 = 0; n2 < 20; n2++) {
        float a0 = As[n2][lid];
        float a1 = As[n2][lid + 256];
        #pragma unroll
        for (int r = 0; r < 20; r++) {
            float2 c = cts[n2*20 + r];
            acc[0][r].x += a0*c.x;  acc[0][r].y += a0*c.y;
            acc[1][r].x += a1*c.x;  acc[1][r].y += a1*c.y;
        }
    }

    int ma = m0 + lid, mb = m0 + lid + 256;
    #pragma unroll
    for (int r = 0; r < 20; r++) {
        int base = (r*32 + n1)*NFRF;
        if (ma < NFRF) g_Z[base + ma] = acc[0][r];
        if (mb < NFRF) g_Z[base + mb] = acc[1][r];
    }
}

// ---------------- fwd stage 2: S[r+20q][m] = sum_n1 Z[n1][r][m] * W32[n1][q]
__global__ void __launch_bounds__(256) k_stage2() {
    __shared__ float2 Zs[16][256];
    __shared__ float2 Bs[32*17];
    int m0 = blockIdx.x * 256;
    int r  = blockIdx.y;
    int lid = threadIdx.x;

    #pragma unroll
    for (int e = lid; e < 32*17; e += 256) Bs[e] = g_W32[e];

    float2 acc[17];
    #pragma unroll
    for (int q = 0; q < 17; q++) acc[q] = make_float2(0.f, 0.f);

    #pragma unroll
    for (int kh = 0; kh < 2; kh++) {
        __syncthreads();
        #pragma unroll
        for (int i = 0; i < 16; i++) {
            int e = i*256 + lid;
            int k = e >> 8, ml = e & 255;
            int m = m0 + ml;
            Zs[k][ml] = (m < NFRF) ? g_Z[(r*32 + kh*16 + k)*NFRF + m]
                                   : make_float2(0.f, 0.f);
        }
        __syncthreads();
        #pragma unroll
        for (int k = 0; k < 16; k++) {
            float2 a = Zs[k][lid];
            int kg = kh*16 + k;
            #pragma unroll
            for (int q = 0; q < 17; q++) {
                float2 b = Bs[kg*17 + q];
                acc[q].x += a.x*b.x - a.y*b.y;
                acc[q].y += a.x*b.y + a.y*b.x;
            }
        }
    }

    int m = m0 + lid;
    if (m < NFRF) {
        #pragma unroll
        for (int q = 0; q < 17; q++) {
            int f = r + 20*q;
            if (f < NF) g_S[f*NFRF + m] = acc[q];
        }
    }
}

// ---------------- covariance features ----------------
__global__ void k_cov(float* __restrict__ out) {
    int idx = blockIdx.x*blockDim.x + threadIdx.x;
    if (idx >= 2*FT) return;
    int t = idx % NT;
    int f = (idx / NT) % NF;
    int b = idx / FT;
    float2 S[8];
    #pragma unroll
    for (int c = 0; c < 8; c++)
        S[c] = g_S[f*NFRF + (b*8 + c)*NT + t];
    float* o = out + OFF_FEATS + (b*74)*FT + f*NT + t;
    int p = 0;
    #pragma unroll
    for (int i = 0; i < 8; i++) {
        #pragma unroll
        for (int j = i; j < 8; j++) {
            float re = S[i].x*S[j].x + S[i].y*S[j].y;   // S_i * conj(S_j)
            float im = S[i].y*S[j].x - S[i].x*S[j].y;
            o[(2*p    )*FT] = re;
            o[(2*p + 1)*FT] = im;
            p++;
        }
    }
    o[72*FT] = S[3].x;
    o[73*FT] = S[3].y;
}

// ---------------- padded refS (b=0) ----------------
__global__ void k_refpad() {
    int idx = blockIdx.x*blockDim.x + threadIdx.x;
    if (idx >= 323*309) return;
    int fp = idx / 309, tp = idx - fp*309;
    int f = fp - 1, t = tp - 4;
    float2 v = make_float2(0.f, 0.f);
    if (f >= 0 && f < NF && t >= 0 && t < NT)
        v = g_S[f*NFRF + 16*NT + t];
    g_rp[idx] = v;
}

// ---------------- deep filtering (b=0 only), freq-major output ----------------
__global__ void k_deepfilter(const float2* __restrict__ rtf) {
    int idx = blockIdx.x*blockDim.x + threadIdx.x;
    if (idx >= 7*FT) return;
    int t = idx % NT;
    int f = (idx / NT) % NF;
    int m = idx / FT;
    const float2* rbase = rtf + m*27*FT + f*NT + t;  // b=0: [m][27][F][T] float2
    float2 acc = make_float2(0.f, 0.f);
    #pragma unroll
    for (int ki = 0; ki < 3; ki++) {
        #pragma unroll
        for (int kj = 0; kj < 9; kj++) {
            float2 r = rbase[(ki*9 + kj)*FT];
            float2 p = g_rp[(f + ki)*309 + (t + kj)];
            acc.x += r.x*p.x - r.y*p.y;
            acc.y += r.x*p.y + r.y*p.x;
        }
    }
    g_estF[f*MINV + m*NT + t] = acc;   // [k][R], R = m*NT + t
}

// ---------------- inv stage A: A1[r][n1][R] = sum_q ck*E[20q+r][R]*e^{+2pi i k n1/640}
// grid (17 m-tiles, 20 r), block 128
__global__ void __launch_bounds__(128) k_istageA() {
    __shared__ float2 Es[17][128];
    __shared__ float2 TAs[17*32];
    int m0 = blockIdx.x * 128;
    int r  = blockIdx.y;
    int lid = threadIdx.x;

    #pragma unroll
    for (int e = lid; e < 544; e += 128) TAs[e] = g_TA[r*544 + e];
    int R = m0 + lid;
    #pragma unroll
    for (int q = 0; q < 17; q++) {
        int k = 20*q + r;
        Es[q][lid] = (k < NF && R < MINV) ? g_estF[k*MINV + R] : make_float2(0.f, 0.f);
    }
    __syncthreads();

    float2 acc[32];
    #pragma unroll
    for (int n1 = 0; n1 < 32; n1++) acc[n1] = make_float2(0.f, 0.f);

    #pragma unroll
    for (int q = 0; q < 17; q++) {
        float2 a = Es[q][lid];
        #pragma unroll
        for (int n1 = 0; n1 < 32; n1++) {
            float2 t = TAs[q*32 + n1];
            acc[n1].x += a.x*t.x - a.y*t.y;
            acc[n1].y += a.x*t.y + a.y*t.x;
        }
    }

    if (R < MINV) {
        #pragma unroll
        for (int n1 = 0; n1 < 32; n1++)
            g_A1[(r*32 + n1)*MINV + R] = acc[n1];
    }
}

// ---------------- inv stage B: y[R][n] = win[n]/640 * Re(sum_r A1[r][n1][R]*e^{+2pi i r n2/20})
// grid ceil(2107/8), block 256; n = n1 + 32*n2
__global__ void __launch_bounds__(256) k_istageB() {
    __shared__ float2 A1s[20][8][33];    // [r][mloc][n1] (pad to 33 for conflict-free)
    __shared__ float2 TBs[400];
    __shared__ float  wins[NFFT];
    int R0 = blockIdx.x * 8;
    int lid = threadIdx.x;

    #pragma unroll
    for (int e = lid; e < 400; e += 256) TBs[e] = g_TB[e];
    #pragma unroll
    for (int e = lid; e < NFFT; e += 256) wins[e] = g_win[e] * (1.0f/640.0f);
    #pragma unroll
    for (int i = 0; i < 20; i++) {
        int e = i*256 + lid;
        int rn1 = e >> 3, mloc = e & 7;
        int r = rn1 >> 5, n1 = rn1 & 31;
        int R = R0 + mloc;
        A1s[r][mloc][n1] = (R < MINV) ? g_A1[rn1*MINV + R] : make_float2(0.f, 0.f);
    }
    __syncthreads();

    #pragma unroll
    for (int mloc = 0; mloc < 8; mloc++) {
        int R = R0 + mloc;
        if (R >= MINV) break;    // uniform across block
        #pragma unroll
        for (int nb = 0; nb < 3; nb++) {
            int n = nb*256 + lid;
            if (n < NFFT) {
                int n1 = n & 31, n2 = n >> 5;
                float acc = 0.0f;
                #pragma unroll
                for (int r = 0; r < 20; r++) {
                    float2 a = A1s[r][mloc][n1];
                    float2 t = TBs[r*20 + n2];
                    acc += a.x*t.x - a.y*t.y;
                }
                g_y[R*NFFT + n] = acc * wins[n];
            }
        }
    }
}

// ---------------- overlap-add + interleave output ----------------
__global__ void k_ola(const float* __restrict__ ref, float* __restrict__ out) {
    int s = blockIdx.x*blockDim.x + threadIdx.x;
    if (s >= TLEN) return;
    int sp = s + HOP;                 // position in uncropped signal
    int t1 = sp / HOP;                // in [1, 300]
    int n1 = sp - t1*HOP;             // [0, 320)
    int t0 = t1 - 1;
    int nn0 = n1 + HOP;               // [320, 640)
    float iw = g_invw[sp];
    float* o = out + s*8;
    #pragma unroll
    for (int m = 0; m < 7; m++) {
        float v = (g_y[(m*NT + t0)*NFFT + nn0] + g_y[(m*NT + t1)*NFFT + n1]) * iw;
        o[m < 3 ? m : m + 1] = v;
    }
    o[3] = ref[s];
}

// ---------------- launch ----------------
extern "C" void kernel_launch(void* const* d_in, const int* in_sizes, int n_in,
                              void* d_out, int out_size) {
    const float*  x   = (const float*)d_in[0];
    const float2* rtf = (const float2*)d_in[1];  // [B][7][3][9][F][T][2]; b=0 slice
    const float*  ref = (const float*)d_in[2];   // [2][1][T]; b=0 slice
    float* out = (float*)d_out;

    k_tab<<<(12800 + 544 + 10880 + 400 + NFFT + 255)/256, 256>>>();
    k_invw<<<(LPAD + 255)/256, 256>>>();
    {
        dim3 g((NFRF + 31)/32, NFFT/32);
        k_framesT<<<g, dim3(32, 8)>>>(x, ref);
    }
    {
        dim3 g((NFRF + 511)/512, 32);
        k_stage1<<<g, 256>>>();
    }
    {
        dim3 g((NFRF + 255)/256, 20);
        k_stage2<<<g, 256>>>();
    }
    k_cov<<<(2*FT + 255)/256, 256>>>(out);
    k_refpad<<<(323*309 + 255)/256, 256>>>();
    k_deepfilter<<<(7*FT + 255)/256, 256>>>(rtf);
    {
        dim3 g((MINV + 127)/128, 20);
        k_istageA<<<g, 128>>>();
    }
    {
        dim3 g((MINV + 7)/8);
        k_istageB<<<g, 256>>>();
    }
    k_ola<<<(TLEN + 255)/256, 256>>>(ref, out);
}